// round 3
// baseline (speedup 1.0000x reference)
#include <cuda_runtime.h>
#include <cstdint>

#define NPTS 1000000
#define NC   128
#define NG   100000

// scratch: group sums (later overwritten with means) + counts
__device__ float g_sums[(size_t)NG * NC];   // 51.2 MB
__device__ float g_counts[NG];

__global__ void zero_kernel() {
    size_t i = (size_t)blockIdx.x * blockDim.x + threadIdx.x;
    if (i < (size_t)NG * NC) g_sums[i] = 0.0f;
    if (i < NG) g_counts[i] = 0.0f;
}

// one warp per point; lane l handles float4 chunk l (32 float4 = 128 floats)
__global__ void accum_kernel(const float4* __restrict__ feat,
                             const int* __restrict__ gid) {
    int warp = (int)((blockIdx.x * (size_t)blockDim.x + threadIdx.x) >> 5);
    int lane = threadIdx.x & 31;
    if (warp >= NPTS) return;
    int g = gid[warp];
    g = (g < 0) ? 0 : (g >= NG ? NG - 1 : g);   // safety clamp
    float4 v = feat[(size_t)warp * 32 + lane];
    float* base = g_sums + (size_t)g * NC + lane * 4;
    atomicAdd(base + 0, v.x);
    atomicAdd(base + 1, v.y);
    atomicAdd(base + 2, v.z);
    atomicAdd(base + 3, v.w);
    if (lane == 0) atomicAdd(&g_counts[g], 1.0f);
}

__global__ void mean_kernel() {
    size_t i = (size_t)blockIdx.x * blockDim.x + threadIdx.x;
    if (i < (size_t)NG * NC) {
        float c = g_counts[i >> 7];  // i / 128
        g_sums[i] *= (1.0f / fmaxf(c, 1.0f));
    }
}

// one warp per point; float4 reads from L2-resident means, coalesced 128B store
__global__ void gather_kernel(const int* __restrict__ gid,
                              float4* __restrict__ out) {
    int warp = (int)((blockIdx.x * (size_t)blockDim.x + threadIdx.x) >> 5);
    int lane = threadIdx.x & 31;
    if (warp >= NPTS) return;
    int g = gid[warp];
    g = (g < 0) ? 0 : (g >= NG ? NG - 1 : g);   // safety clamp
    const float4* m = reinterpret_cast<const float4*>(g_sums) + (size_t)g * 32;
    out[(size_t)warp * 32 + lane] = m[lane];
}

extern "C" void kernel_launch(void* const* d_in, const int* in_sizes, int n_in,
                              void* d_out, int out_size) {
    // inputs: [0] ref_bxyz f32 [N,4] (unused), [1] ref_feat f32 [N,128],
    //         [2] group_ids (int32 — JAX x64 disabled downcasts the requested int64)
    const float4* feat = (const float4*)d_in[1];
    const int*    gid  = (const int*)d_in[2];
    float4*       out  = (float4*)d_out;

    const int T = 256;
    size_t zero_elems = (size_t)NG * NC;
    zero_kernel<<<(unsigned)((zero_elems + T - 1) / T), T>>>();

    // warp per point: NPTS warps = NPTS*32 threads
    size_t accum_threads = (size_t)NPTS * 32;
    accum_kernel<<<(unsigned)((accum_threads + T - 1) / T), T>>>(feat, gid);

    mean_kernel<<<(unsigned)((zero_elems + T - 1) / T), T>>>();

    gather_kernel<<<(unsigned)((accum_threads + T - 1) / T), T>>>(gid, out);
}

// round 4
// speedup vs baseline: 2.0372x; 2.0372x over previous
#include <cuda_runtime.h>
#include <cstdint>

#define NPTS 1000000
#define NC   128
#define NG   100000

// scratch: group sums + counts (zeroed each launch; graph-replay safe)
__device__ float4 g_sums[(size_t)NG * 32];   // 51.2 MB, [G][32] float4
__device__ float  g_counts[NG];

__global__ void zero_kernel() {
    size_t i = (size_t)blockIdx.x * blockDim.x + threadIdx.x;
    if (i < (size_t)NG * 32) g_sums[i] = make_float4(0.f, 0.f, 0.f, 0.f);
    if (i < NG) g_counts[i] = 0.0f;
}

__device__ __forceinline__ void red_add_v4(float* addr, float4 v) {
    asm volatile("red.global.add.v4.f32 [%0], {%1, %2, %3, %4};"
                 :: "l"(addr), "f"(v.x), "f"(v.y), "f"(v.z), "f"(v.w)
                 : "memory");
}

// one warp per 4 points; lane l handles float4 chunk l of each point
__global__ void accum_kernel(const float4* __restrict__ feat,
                             const int* __restrict__ gid) {
    int warp = (int)((blockIdx.x * (size_t)blockDim.x + threadIdx.x) >> 5);
    int lane = threadIdx.x & 31;
    int p0 = warp * 4;
    if (p0 >= NPTS) return;

    int g[4];
    float4 v[4];
#pragma unroll
    for (int j = 0; j < 4; j++) g[j] = __ldg(&gid[p0 + j]);
#pragma unroll
    for (int j = 0; j < 4; j++) v[j] = feat[(size_t)(p0 + j) * 32 + lane];
#pragma unroll
    for (int j = 0; j < 4; j++) {
        float* base = reinterpret_cast<float*>(g_sums + (size_t)g[j] * 32 + lane);
        red_add_v4(base, v[j]);
    }
    if (lane == 0) {
#pragma unroll
        for (int j = 0; j < 4; j++) atomicAdd(&g_counts[g[j]], 1.0f);  // no-return -> REDG
    }
}

// fused mean + gather: out[p] = sums[g] * 1/max(count[g],1)
__global__ void gather_kernel(const int* __restrict__ gid,
                              float4* __restrict__ out) {
    int warp = (int)((blockIdx.x * (size_t)blockDim.x + threadIdx.x) >> 5);
    int lane = threadIdx.x & 31;
    int p0 = warp * 4;
    if (p0 >= NPTS) return;

    int g[4];
#pragma unroll
    for (int j = 0; j < 4; j++) g[j] = __ldg(&gid[p0 + j]);

    float4 v[4];
#pragma unroll
    for (int j = 0; j < 4; j++) v[j] = g_sums[(size_t)g[j] * 32 + lane];  // L2-resident

    float rinv[4];
#pragma unroll
    for (int j = 0; j < 4; j++) rinv[j] = __frcp_rn(fmaxf(g_counts[g[j]], 1.0f));

#pragma unroll
    for (int j = 0; j < 4; j++) {
        float4 r = make_float4(v[j].x * rinv[j], v[j].y * rinv[j],
                               v[j].z * rinv[j], v[j].w * rinv[j]);
        out[(size_t)(p0 + j) * 32 + lane] = r;
    }
}

extern "C" void kernel_launch(void* const* d_in, const int* in_sizes, int n_in,
                              void* d_out, int out_size) {
    // inputs: [0] ref_bxyz f32 [N,4] (unused), [1] ref_feat f32 [N,128],
    //         [2] group_ids int32 [N]
    const float4* feat = (const float4*)d_in[1];
    const int*    gid  = (const int*)d_in[2];
    float4*       out  = (float4*)d_out;

    const int T = 256;
    size_t zero_elems = (size_t)NG * 32;  // float4 elements
    zero_kernel<<<(unsigned)((zero_elems + T - 1) / T), T>>>();

    // NPTS/4 warps of work, 32 threads each
    size_t warps = (NPTS + 3) / 4;
    size_t threads = warps * 32;
    unsigned blocks = (unsigned)((threads + T - 1) / T);
    accum_kernel<<<blocks, T>>>(feat, gid);
    gather_kernel<<<blocks, T>>>(gid, out);
}